// round 2
// baseline (speedup 1.0000x reference)
#include <cuda_runtime.h>
#include <math.h>

#define Bq   32
#define Tt   1024
#define Dd   512
#define Hh   512
#define Vv   64
#define Ss   128
#define XD   576      /* V + H */
#define G4   2048     /* 4*H  */
#define NBLK 128
#define NTHR 256

// ---------------- device scratch (no allocation allowed) ----------------
__device__ float g_h[Bq][Hh];
__device__ float g_c[2][Bq][Hh];
__device__ float g_x[Bq][XD];
__device__ float g_gates[Bq][G4];
__device__ float g_e[Bq][Tt];
__device__ float g_pm[Bq][32];
__device__ float g_ps[Bq][32];
__device__ float g_pv[Bq][32][Dd];

__device__ unsigned g_cnt = 0;
__device__ volatile unsigned g_gen = 0;

// Software grid barrier. All NBLK blocks are resident (1 block/SM max usage),
// so spinning is deadlock-free.
__device__ __forceinline__ void grid_sync() {
    __syncthreads();
    if (threadIdx.x == 0) {
        __threadfence();
        unsigned gen = g_gen;
        if (atomicAdd(&g_cnt, 1) == gridDim.x - 1) {
            atomicExch(&g_cnt, 0);
            __threadfence();
            g_gen = gen + 1;
        } else {
            while (g_gen == gen) { __nanosleep(64); }
        }
        __threadfence();
    }
    __syncthreads();
}

__device__ __forceinline__ float dot4(float4 a, float4 b) {
    return a.x * b.x + a.y * b.y + a.z * b.z + a.w * b.w;
}

__global__ void __launch_bounds__(NTHR, 1) speller_kernel(
    const float* __restrict__ L,      // [B,T,D]
    const float* __restrict__ W_ih,   // [4H, XD]
    const float* __restrict__ W_hh,   // [4H, H]
    const float* __restrict__ b_ih,   // [4H]
    const float* __restrict__ b_hh,   // [4H]
    const float* __restrict__ W_out,  // [V, 2H]
    const float* __restrict__ b_out,  // [V]
    float* __restrict__ out_logp,     // [S,B,V]
    float* __restrict__ out_attn)     // [S,B,T]
{
    const int tid  = threadIdx.x;
    const int bid  = blockIdx.x;
    const int wid  = tid >> 5;
    const int lane = tid & 31;
    const int b    = bid >> 2;   // 0..31
    const int part = bid & 3;    // 0..3  (t-chunk of 256)

    __shared__ __align__(16) float s_xh[XD + Hh];   // P1: [x | h]
    __shared__ __align__(16) float s_h[Hh];         // P2: h (recomputed per block)
    __shared__ __align__(16) float s_hc[2 * Hh];    // P3: [h | ctx]
    __shared__ float s_logits[Vv];
    __shared__ float s_wgt[32];
    __shared__ float s_MS[2];

    // ---------------- init carries ----------------
    for (int i = bid * NTHR + tid; i < Bq * Hh; i += NBLK * NTHR) {
        (&g_h[0][0])[i]    = 0.f;
        (&g_c[0][0][0])[i] = 0.f;
    }
    // x0 = [onehot(0), listener_feature[:,0,:]]
    for (int i = bid * NTHR + tid; i < Bq * XD; i += NBLK * NTHR) {
        int bb = i / XD, k = i - bb * XD;
        g_x[bb][k] = (k < Vv) ? (k == 0 ? 1.f : 0.f)
                              : L[(size_t)bb * Tt * Dd + (k - Vv)];
    }
    grid_sync();

    for (int s = 0; s < Ss; ++s) {
        const int crd = s & 1, cwr = crd ^ 1;

        // ================= P1: LSTM gates [32,2048] =================
        {
            for (int k = tid; k < XD; k += NTHR) s_xh[k]      = g_x[b][k];
            for (int k = tid; k < Hh; k += NTHR) s_xh[XD + k] = g_h[b][k];
            __syncthreads();
            const float4* xv4 = (const float4*)s_xh;          // 144 float4 (x)
            const float4* hv4 = (const float4*)(s_xh + XD);   // 128 float4 (h)
            const int jbase = part * 512 + wid * 64;
            for (int jj = 0; jj < 64; ++jj) {
                const int j = jbase + jj;
                const float4* wi = (const float4*)(W_ih + (size_t)j * XD);
                const float4* wh = (const float4*)(W_hh + (size_t)j * Hh);
                float acc = 0.f;
#pragma unroll
                for (int i = 0; i < 4; ++i)
                    acc += dot4(wi[lane + 32 * i], xv4[lane + 32 * i]);
                if (lane < 16)
                    acc += dot4(wi[128 + lane], xv4[128 + lane]);
#pragma unroll
                for (int i = 0; i < 4; ++i)
                    acc += dot4(wh[lane + 32 * i], hv4[lane + 32 * i]);
#pragma unroll
                for (int o = 16; o; o >>= 1)
                    acc += __shfl_xor_sync(0xffffffffu, acc, o);
                if (lane == 0) g_gates[b][j] = acc + b_ih[j] + b_hh[j];
            }
        }
        grid_sync();

        // ===== P2: LSTM cell update + single-pass (flash) attention =====
        {
            // h recomputed redundantly per block (cheap); chunk-0 block
            // commits c_new (double-buffered) and h to global.
            for (int k = tid; k < Hh; k += NTHR) {
                float ig = g_gates[b][k];
                float fg = g_gates[b][Hh + k];
                float gg = g_gates[b][2 * Hh + k];
                float og = g_gates[b][3 * Hh + k];
                float iv = 1.f / (1.f + expf(-ig));
                float fv = 1.f / (1.f + expf(-fg));
                float gv = tanhf(gg);
                float ov = 1.f / (1.f + expf(-og));
                float cn = fv * g_c[crd][b][k] + iv * gv;
                float hn = ov * tanhf(cn);
                s_h[k] = hn;
                if (part == 0) { g_c[cwr][b][k] = cn; g_h[b][k] = hn; }
            }
            __syncthreads();

            const float* Lb = L + (size_t)b * Tt * Dd;
            const int t0 = part * 256 + wid * 32;
            const float4* sh4 = (const float4*)s_h;
            const float4 h0 = sh4[lane], h1 = sh4[32 + lane],
                         h2 = sh4[64 + lane], h3 = sh4[96 + lane];
            float m = -INFINITY, ss = 0.f;
            float4 v0 = {0,0,0,0}, v1 = v0, v2 = v0, v3 = v0;

            for (int it = 0; it < 32; ++it) {
                const int t = t0 + it;
                const float4* Lt = (const float4*)(Lb + (size_t)t * Dd);
                float4 a0 = Lt[lane], a1 = Lt[32 + lane],
                       a2 = Lt[64 + lane], a3 = Lt[96 + lane];
                float e = dot4(a0, h0) + dot4(a1, h1) + dot4(a2, h2) + dot4(a3, h3);
#pragma unroll
                for (int o = 16; o; o >>= 1)
                    e += __shfl_xor_sync(0xffffffffu, e, o);
                if (lane == 0) g_e[b][t] = e;
                if (e > m) {                       // uniform across warp
                    float sc = expf(m - e);        // first iter: exp(-inf)=0
                    ss = ss * sc + 1.f;
                    v0.x = v0.x*sc + a0.x; v0.y = v0.y*sc + a0.y; v0.z = v0.z*sc + a0.z; v0.w = v0.w*sc + a0.w;
                    v1.x = v1.x*sc + a1.x; v1.y = v1.y*sc + a1.y; v1.z = v1.z*sc + a1.z; v1.w = v1.w*sc + a1.w;
                    v2.x = v2.x*sc + a2.x; v2.y = v2.y*sc + a2.y; v2.z = v2.z*sc + a2.z; v2.w = v2.w*sc + a2.w;
                    v3.x = v3.x*sc + a3.x; v3.y = v3.y*sc + a3.y; v3.z = v3.z*sc + a3.z; v3.w = v3.w*sc + a3.w;
                    m = e;
                } else {
                    float w = expf(e - m);
                    ss += w;
                    v0.x += w*a0.x; v0.y += w*a0.y; v0.z += w*a0.z; v0.w += w*a0.w;
                    v1.x += w*a1.x; v1.y += w*a1.y; v1.z += w*a1.z; v1.w += w*a1.w;
                    v2.x += w*a2.x; v2.y += w*a2.y; v2.z += w*a2.z; v2.w += w*a2.w;
                    v3.x += w*a3.x; v3.y += w*a3.y; v3.z += w*a3.z; v3.w += w*a3.w;
                }
            }
            const int p = part * 8 + wid;          // 32 partials per b
            float4* pv4 = (float4*)g_pv[b][p];
            pv4[lane] = v0; pv4[32 + lane] = v1; pv4[64 + lane] = v2; pv4[96 + lane] = v3;
            if (lane == 0) { g_pm[b][p] = m; g_ps[b][p] = ss; }
        }
        grid_sync();

        // ===== P3 (32 blocks): merge softmax, ctx, record, logits, argmax =====
        if (bid < Bq) {
            const int bb = bid;
            if (tid < 32) {
                float mi = g_pm[bb][tid];
                float M = mi;
#pragma unroll
                for (int o = 16; o; o >>= 1)
                    M = fmaxf(M, __shfl_xor_sync(0xffffffffu, M, o));
                float w = expf(mi - M);
                s_wgt[tid] = w;
                float sw = g_ps[bb][tid] * w;
#pragma unroll
                for (int o = 16; o; o >>= 1)
                    sw += __shfl_xor_sync(0xffffffffu, sw, o);
                if (tid == 0) { s_MS[0] = M; s_MS[1] = sw; }
            }
            __syncthreads();
            const float M = s_MS[0], invS = 1.f / s_MS[1];

            for (int d = tid; d < Dd; d += NTHR) {
                float acc = 0.f;
#pragma unroll 8
                for (int p2 = 0; p2 < 32; ++p2)
                    acc += g_pv[bb][p2][d] * s_wgt[p2];
                float ctx = acc * invS;
                s_hc[Hh + d]   = ctx;
                g_x[bb][Vv + d] = ctx;            // feedback input (ctx part)
            }
            for (int k = tid; k < Hh; k += NTHR) s_hc[k] = g_h[bb][k];

            float* rec = out_attn + ((size_t)s * Bq + bb) * Tt;
            for (int t = tid; t < Tt; t += NTHR)
                rec[t] = expf(g_e[bb][t] - M) * invS;
            __syncthreads();

            for (int r = wid; r < Vv; r += 8) {
                const float4* wr  = (const float4*)(W_out + (size_t)r * 2 * Hh);
                const float4* hc4 = (const float4*)s_hc;
                float acc = 0.f;
#pragma unroll
                for (int i = 0; i < 8; ++i)
                    acc += dot4(wr[lane + 32 * i], hc4[lane + 32 * i]);
#pragma unroll
                for (int o = 16; o; o >>= 1)
                    acc += __shfl_xor_sync(0xffffffffu, acc, o);
                if (lane == 0) s_logits[r] = acc + b_out[r];
            }
            __syncthreads();

            if (tid < 32) {
                float z0 = s_logits[tid], z1 = s_logits[32 + tid];
                float zm = fmaxf(z0, z1);
#pragma unroll
                for (int o = 16; o; o >>= 1)
                    zm = fmaxf(zm, __shfl_xor_sync(0xffffffffu, zm, o));
                float es = expf(z0 - zm) + expf(z1 - zm);
#pragma unroll
                for (int o = 16; o; o >>= 1)
                    es += __shfl_xor_sync(0xffffffffu, es, o);
                float lse = zm + logf(es);
                float* lp = out_logp + ((size_t)s * Bq + bb) * Vv;
                lp[tid]      = z0 - lse;
                lp[32 + tid] = z1 - lse;
                // argmax, first-index tie-break (matches jnp.argmax)
                float bv; int bi2;
                if (z1 > z0) { bv = z1; bi2 = 32 + tid; } else { bv = z0; bi2 = tid; }
#pragma unroll
                for (int o = 16; o; o >>= 1) {
                    float ov = __shfl_xor_sync(0xffffffffu, bv, o);
                    int   oi = __shfl_xor_sync(0xffffffffu, bi2, o);
                    if (ov > bv || (ov == bv && oi < bi2)) { bv = ov; bi2 = oi; }
                }
                g_x[bb][tid]      = (tid == bi2)      ? 1.f : 0.f;
                g_x[bb][32 + tid] = (32 + tid == bi2) ? 1.f : 0.f;
            }
        }
        grid_sync();
    }
}

extern "C" void kernel_launch(void* const* d_in, const int* in_sizes, int n_in,
                              void* d_out, int out_size) {
    const float* L     = (const float*)d_in[0];
    const float* W_ih  = (const float*)d_in[1];
    const float* W_hh  = (const float*)d_in[2];
    const float* b_ih  = (const float*)d_in[3];
    const float* b_hh  = (const float*)d_in[4];
    const float* W_out = (const float*)d_in[5];
    const float* b_out = (const float*)d_in[6];
    float* out_logp = (float*)d_out;                            // [S,B,V]
    float* out_attn = (float*)d_out + (size_t)Ss * Bq * Vv;     // [S,B,T]
    speller_kernel<<<NBLK, NTHR>>>(L, W_ih, W_hh, b_ih, b_hh, W_out, b_out,
                                   out_logp, out_attn);
}

// round 3
// speedup vs baseline: 1.0817x; 1.0817x over previous
#include <cuda_runtime.h>
#include <math.h>

#define Bq   32
#define Tt   1024
#define Dd   512
#define Hh   512
#define Vv   64
#define Ss   128
#define XD   576      /* V + H */
#define KK   1088     /* XD + H combined gemm-k */
#define G4   2048     /* 4*H  */
#define NBLK 128
#define NTHR 512

typedef unsigned long long ull;

// ---------------- device scratch (no allocation allowed) ----------------
__device__ float g_xh[Bq][KK];          // [onehot(64) | ctx(512) | h(512)]
__device__ float g_c[2][Bq][Hh];
__device__ float g_gates[Bq][G4];
__device__ float g_e[Bq][Tt];
__device__ float g_pm[Bq * 4];
__device__ float g_ps[Bq * 4];
__device__ float g_pvm[Bq][4][Dd];

__device__ unsigned g_cnt = 0;
__device__ volatile unsigned g_gen = 0;

__device__ __forceinline__ void grid_sync() {
    __syncthreads();
    if (threadIdx.x == 0) {
        __threadfence();
        unsigned gen = g_gen;
        if (atomicAdd(&g_cnt, 1) == gridDim.x - 1) {
            atomicExch(&g_cnt, 0);
            __threadfence();
            g_gen = gen + 1;
        } else {
            while (g_gen == gen) { __nanosleep(64); }
        }
        __threadfence();
    }
    __syncthreads();
}

// ---- packed f32x2 helpers (FFMA2: ptxas never emits; PTX-only) ----
__device__ __forceinline__ ull fma2(ull a, ull b, ull c) {
    ull d; asm("fma.rn.f32x2 %0,%1,%2,%3;" : "=l"(d) : "l"(a), "l"(b), "l"(c));
    return d;
}
__device__ __forceinline__ ull mul2(ull a, ull b) {
    ull d; asm("mul.rn.f32x2 %0,%1,%2;" : "=l"(d) : "l"(a), "l"(b));
    return d;
}
__device__ __forceinline__ ull pk2(float x, float y) {
    ull d; asm("mov.b64 %0,{%1,%2};" : "=l"(d) : "f"(x), "f"(y));
    return d;
}
__device__ __forceinline__ float2 unpk(ull v) {
    float2 r; asm("mov.b64 {%0,%1},%2;" : "=f"(r.x), "=f"(r.y) : "l"(v));
    return r;
}
__device__ __forceinline__ float wsum(float v) {
#pragma unroll
    for (int o = 16; o; o >>= 1) v += __shfl_xor_sync(0xffffffffu, v, o);
    return v;
}
__device__ __forceinline__ float wmax(float v) {
#pragma unroll
    for (int o = 16; o; o >>= 1) v = fmaxf(v, __shfl_xor_sync(0xffffffffu, v, o));
    return v;
}

__global__ void __launch_bounds__(NTHR, 1) speller_kernel(
    const float* __restrict__ L,      // [B,T,D]
    const float* __restrict__ W_ih,   // [4H, XD]
    const float* __restrict__ W_hh,   // [4H, H]
    const float* __restrict__ b_ih,   // [4H]
    const float* __restrict__ b_hh,   // [4H]
    const float* __restrict__ W_out,  // [V, 2H]
    const float* __restrict__ b_out,  // [V]
    float* __restrict__ out_logp,     // [S,B,V]
    float* __restrict__ out_attn)     // [S,B,T]
{
    const int tid  = threadIdx.x;
    const int bid  = blockIdx.x;
    const int wid  = tid >> 5;
    const int lane = tid & 31;

    extern __shared__ float sm[];
    float* s_xh     = sm;            // 16*1088 floats (P1 X-slab; reused as s_pv 16*512 in P2)
    float* s_h      = sm + 17408;    // 512
    float* s_hc     = sm + 17920;    // 1024
    float* s_pm     = sm + 18944;    // 16
    float* s_ps     = sm + 18960;    // 16
    float* s_wgt    = sm + 18976;    // 16
    float* s_logits = sm + 18992;    // 64
    float* s_MS     = sm + 19056;    // 2

    // ---------------- init carries ----------------
    for (int i = bid * NTHR + tid; i < Bq * Hh; i += NBLK * NTHR)
        (&g_c[0][0][0])[i] = 0.f;
    for (int i = bid * NTHR + tid; i < Bq * KK; i += NBLK * NTHR) {
        int bb = i / KK, k = i - bb * KK;
        float v = 0.f;
        if (k == 0) v = 1.f;                                   // onehot class 0
        else if (k >= Vv && k < XD) v = L[(size_t)bb * Tt * Dd + (k - Vv)];
        g_xh[bb][k] = v;                                       // h part = 0
    }
    grid_sync();

    for (int s = 0; s < Ss; ++s) {
        const int crd = s & 1, cwr = crd ^ 1;

        // ===== P1: gates[32,2048] = Xh[32,1088] @ [W_ih|W_hh]^T, batch-amortized =====
        {
            const int b0  = (bid & 1) << 4;          // 0 or 16
            const int j00 = (bid >> 1) << 5;         // 64 j-tiles of 32

            // stage 16 batch rows of Xh into smem (70KB), coalesced
            const float4* src = (const float4*)(&g_xh[b0][0]);
            float4* dst = (float4*)s_xh;
            for (int idx = tid; idx < 16 * 272; idx += NTHR) dst[idx] = src[idx];
            __syncthreads();

#pragma unroll
            for (int tk = 0; tk < 2; ++tk) {
                const int task = (wid << 1) | tk;             // 0..31
                const int jg = task >> 3, bg = task & 7;
                const int jbase = j00 + (jg << 3);
                const char* sx0 = (const char*)(s_xh + (bg * 2 + 0) * KK);
                const char* sx1 = (const char*)(s_xh + (bg * 2 + 1) * KK);
                const char* bI0 = (const char*)(W_ih + (size_t)jbase * XD);
                const char* bH0 = (const char*)(W_hh + (size_t)jbase * Hh) - 144 * 16;

                ull acc[8][2];
#pragma unroll
                for (int jj = 0; jj < 8; ++jj) { acc[jj][0] = 0ull; acc[jj][1] = 0ull; }

#pragma unroll
                for (int i = 0; i < 9; ++i) {
                    const int c = lane + (i << 5);            // float4 index 0..271
                    if (c < 272) {
                        const size_t off = (size_t)c << 4;
                        ulonglong2 x0 = *(const ulonglong2*)(sx0 + off);
                        ulonglong2 x1 = *(const ulonglong2*)(sx1 + off);
                        const bool ih = (c < 144);
                        const char* wp = (ih ? bI0 : bH0) + off;
                        const long rs  = ih ? (XD * 4) : (Hh * 4);
#pragma unroll
                        for (int jj = 0; jj < 8; ++jj) {
                            ulonglong2 w = *(const ulonglong2*)wp; wp += rs;
                            acc[jj][0] = fma2(w.x, x0.x, acc[jj][0]);
                            acc[jj][0] = fma2(w.y, x0.y, acc[jj][0]);
                            acc[jj][1] = fma2(w.x, x1.x, acc[jj][1]);
                            acc[jj][1] = fma2(w.y, x1.y, acc[jj][1]);
                        }
                    }
                }
                const int bgl = b0 + (bg << 1);
#pragma unroll
                for (int jj = 0; jj < 8; ++jj) {
                    const int j = jbase + jj;
                    const float bsum = b_ih[j] + b_hh[j];
#pragma unroll
                    for (int bb = 0; bb < 2; ++bb) {
                        float2 p = unpk(acc[jj][bb]);
                        float v = wsum(p.x + p.y);
                        if (lane == 0) g_gates[bgl + bb][j] = v + bsum;
                    }
                }
            }
        }
        grid_sync();

        // ===== P2: LSTM cell + single-pass flash attention (16 warps x 16 t) =====
        {
            const int b = bid >> 2, part = bid & 3;
            // cell update: one element per thread
            {
                const int k = tid;
                float ig = g_gates[b][k];
                float fg = g_gates[b][Hh + k];
                float gg = g_gates[b][2 * Hh + k];
                float og = g_gates[b][3 * Hh + k];
                float iv = 1.f / (1.f + __expf(-ig));
                float fv = 1.f / (1.f + __expf(-fg));
                float gv = tanhf(gg);
                float ov = 1.f / (1.f + __expf(-og));
                float cn = fv * g_c[crd][b][k] + iv * gv;
                float hn = ov * tanhf(cn);
                s_h[k] = hn;
                if (part == 0) { g_c[cwr][b][k] = cn; g_xh[b][XD + k] = hn; }
            }
            __syncthreads();

            // pack h into registers
            ull H[8];
            {
                const ulonglong2* h2 = (const ulonglong2*)s_h;
#pragma unroll
                for (int q = 0; q < 4; ++q) {
                    ulonglong2 t = h2[lane + (q << 5)];
                    H[2 * q] = t.x; H[2 * q + 1] = t.y;
                }
            }
            const float* Lb = L + (size_t)b * Tt * Dd;
            const int t0 = part * 256 + wid * 16;
            float m = -INFINITY, ss = 0.f;
            ull V[8];
#pragma unroll
            for (int r = 0; r < 8; ++r) V[r] = 0ull;

            for (int it = 0; it < 16; ++it) {
                const int t = t0 + it;
                const ulonglong2* Lt = (const ulonglong2*)(Lb + (size_t)t * Dd);
                ulonglong2 A0 = Lt[lane], A1 = Lt[lane + 32],
                           A2 = Lt[lane + 64], A3 = Lt[lane + 96];
                ull e2 = mul2(A0.x, H[0]);
                e2 = fma2(A0.y, H[1], e2);
                e2 = fma2(A1.x, H[2], e2);
                e2 = fma2(A1.y, H[3], e2);
                e2 = fma2(A2.x, H[4], e2);
                e2 = fma2(A2.y, H[5], e2);
                e2 = fma2(A3.x, H[6], e2);
                e2 = fma2(A3.y, H[7], e2);
                float2 ef = unpk(e2);
                float e = wsum(ef.x + ef.y);
                if (lane == 0) g_e[b][t] = e;
                if (e > m) {
                    float sc = __expf(m - e);        // first iter: exp(-inf)=0
                    ull sc2 = pk2(sc, sc);
                    ss = ss * sc + 1.f;
                    V[0] = fma2(V[0], sc2, A0.x); V[1] = fma2(V[1], sc2, A0.y);
                    V[2] = fma2(V[2], sc2, A1.x); V[3] = fma2(V[3], sc2, A1.y);
                    V[4] = fma2(V[4], sc2, A2.x); V[5] = fma2(V[5], sc2, A2.y);
                    V[6] = fma2(V[6], sc2, A3.x); V[7] = fma2(V[7], sc2, A3.y);
                    m = e;
                } else {
                    float w = __expf(e - m);
                    ull w2 = pk2(w, w);
                    ss += w;
                    V[0] = fma2(A0.x, w2, V[0]); V[1] = fma2(A0.y, w2, V[1]);
                    V[2] = fma2(A1.x, w2, V[2]); V[3] = fma2(A1.y, w2, V[3]);
                    V[4] = fma2(A2.x, w2, V[4]); V[5] = fma2(A2.y, w2, V[5]);
                    V[6] = fma2(A3.x, w2, V[6]); V[7] = fma2(A3.y, w2, V[7]);
                }
            }
            // per-warp partial -> smem (reuse s_xh region as s_pv[16][512])
            float* s_pv = s_xh;
            {
                ulonglong2* pvrow = (ulonglong2*)(s_pv + (wid << 9));
#pragma unroll
                for (int q = 0; q < 4; ++q) {
                    ulonglong2 t2; t2.x = V[2 * q]; t2.y = V[2 * q + 1];
                    pvrow[lane + (q << 5)] = t2;
                }
                if (lane == 0) { s_pm[wid] = m; s_ps[wid] = ss; }
            }
            __syncthreads();
            // block-level scalar merge (warp 0)
            if (wid == 0) {
                float mi = (lane < 16) ? s_pm[lane] : -INFINITY;
                float M = wmax(mi);
                float wg = (lane < 16) ? __expf(mi - M) : 0.f;
                if (lane < 16) s_wgt[lane] = wg;
                float sw = wsum((lane < 16) ? s_ps[lane] * wg : 0.f);
                if (lane == 0) { g_pm[b * 4 + part] = M; g_ps[b * 4 + part] = sw; }
            }
            __syncthreads();
            // block-level v merge: one d per thread
            {
                float acc = 0.f;
#pragma unroll
                for (int w = 0; w < 16; ++w)
                    acc += s_wgt[w] * s_pv[(w << 9) + tid];
                g_pvm[b][part][tid] = acc;
            }
        }
        grid_sync();

        // ===== P3 (32 blocks): global merge, record, logits, argmax =====
        if (bid < Bq) {
            const int bb = bid;
            if (wid == 0) {
                float mi = (lane < 4) ? g_pm[bb * 4 + lane] : -INFINITY;
                float M = wmax(mi);
                float wg = (lane < 4) ? __expf(mi - M) : 0.f;
                if (lane < 4) s_wgt[lane] = wg;
                float S = wsum((lane < 4) ? g_ps[bb * 4 + lane] * wg : 0.f);
                if (lane == 0) { s_MS[0] = M; s_MS[1] = 1.f / S; }
            }
            __syncthreads();
            const float M = s_MS[0], invS = s_MS[1];

            // ctx merge (4 partials), h load, attention record
            {
                float acc = 0.f;
#pragma unroll
                for (int p = 0; p < 4; ++p)
                    acc += s_wgt[p] * g_pvm[bb][p][tid];
                float ctx = acc * invS;
                s_hc[Hh + tid] = ctx;
                g_xh[bb][Vv + tid] = ctx;                 // feedback ctx
                s_hc[tid] = g_xh[bb][XD + tid];           // h
                float* rec = out_attn + ((size_t)s * Bq + bb) * Tt;
                rec[tid]       = __expf(g_e[bb][tid]       - M) * invS;
                rec[tid + 512] = __expf(g_e[bb][tid + 512] - M) * invS;
            }
            __syncthreads();

            // logits: 16 warps x 4 rows, packed dot over 1024
            {
                ull C[16];
                const ulonglong2* hc2 = (const ulonglong2*)s_hc;
#pragma unroll
                for (int q = 0; q < 8; ++q) {
                    ulonglong2 t2 = hc2[lane + (q << 5)];
                    C[2 * q] = t2.x; C[2 * q + 1] = t2.y;
                }
#pragma unroll
                for (int rr = 0; rr < 4; ++rr) {
                    const int r = (wid << 2) | rr;
                    const ulonglong2* wr = (const ulonglong2*)(W_out + (size_t)r * 2 * Hh);
                    ull e2 = 0ull;
#pragma unroll
                    for (int q = 0; q < 8; ++q) {
                        ulonglong2 w2 = wr[lane + (q << 5)];
                        e2 = fma2(w2.x, C[2 * q], e2);
                        e2 = fma2(w2.y, C[2 * q + 1], e2);
                    }
                    float2 p = unpk(e2);
                    float v = wsum(p.x + p.y);
                    if (lane == 0) s_logits[r] = v + b_out[r];
                }
            }
            __syncthreads();

            if (tid < 32) {
                float z0 = s_logits[tid], z1 = s_logits[32 + tid];
                float zm = wmax(fmaxf(z0, z1));
                float es = wsum(__expf(z0 - zm) + __expf(z1 - zm));
                float lse = zm + logf(es);
                float* lp = out_logp + ((size_t)s * Bq + bb) * Vv;
                lp[tid]      = z0 - lse;
                lp[32 + tid] = z1 - lse;
                // argmax, first-index tie-break
                float bv; int bi2;
                if (z1 > z0) { bv = z1; bi2 = 32 + tid; } else { bv = z0; bi2 = tid; }
#pragma unroll
                for (int o = 16; o; o >>= 1) {
                    float ov = __shfl_xor_sync(0xffffffffu, bv, o);
                    int   oi = __shfl_xor_sync(0xffffffffu, bi2, o);
                    if (ov > bv || (ov == bv && oi < bi2)) { bv = ov; bi2 = oi; }
                }
                g_xh[bb][tid]      = (tid == bi2)      ? 1.f : 0.f;
                g_xh[bb][32 + tid] = (32 + tid == bi2) ? 1.f : 0.f;
            }
        }
        grid_sync();
    }
}

extern "C" void kernel_launch(void* const* d_in, const int* in_sizes, int n_in,
                              void* d_out, int out_size) {
    const float* L     = (const float*)d_in[0];
    const float* W_ih  = (const float*)d_in[1];
    const float* W_hh  = (const float*)d_in[2];
    const float* b_ih  = (const float*)d_in[3];
    const float* b_hh  = (const float*)d_in[4];
    const float* W_out = (const float*)d_in[5];
    const float* b_out = (const float*)d_in[6];
    float* out_logp = (float*)d_out;                            // [S,B,V]
    float* out_attn = (float*)d_out + (size_t)Ss * Bq * Vv;     // [S,B,T]
    const int smem_bytes = 19058 * 4;
    cudaFuncSetAttribute(speller_kernel,
                         cudaFuncAttributeMaxDynamicSharedMemorySize, smem_bytes);
    speller_kernel<<<NBLK, NTHR, smem_bytes>>>(L, W_ih, W_hh, b_ih, b_hh,
                                               W_out, b_out, out_logp, out_attn);
}

// round 5
// speedup vs baseline: 2.3973x; 2.2162x over previous
#include <cuda_runtime.h>
#include <math.h>

#define Bq   32
#define Tt   1024
#define Dd   512
#define Hh   512
#define Vv   64
#define Ss   128
#define XD   576      /* V + H */
#define KK   1088     /* XD + H */
#define G4   2048
#define NBLK 128
#define NTHR 512

typedef unsigned long long ull;

// smem layout (float offsets)
#define OFF_A   0        /* 34944: P1 sX[32][1092]; P2 s_pv[16][512] */
#define OFF_B   34944    /* 17408: P1 sW[16][1088]; P1 sp[16][8][32] */
#define OFF_H   52352    /* 512  */
#define OFF_HC  52864    /* 1024 */
#define OFF_PM  53888    /* 16   */
#define OFF_PS  53904    /* 16   */
#define OFF_WGT 53920    /* 16   */
#define OFF_LOG 53936    /* 64   */
#define OFF_MS  54000    /* 2    */
#define SMEM_FLOATS 54002

// ---------------- device scratch ----------------
__device__ float g_xh[Bq][KK];          // [onehot(64) | ctx(512) | h(512)]
__device__ float g_c[2][Bq][Hh];
__device__ float g_gates[Bq][G4];
__device__ float g_e[Bq][Tt];
__device__ float g_pm[Bq * 4];
__device__ float g_ps[Bq * 4];
__device__ float g_pvm[Bq][4][Dd];

__device__ unsigned g_cnt = 0;
__device__ volatile unsigned g_gen = 0;

__device__ __forceinline__ void grid_sync() {
    __syncthreads();
    if (threadIdx.x == 0) {
        __threadfence();
        unsigned gen = g_gen;
        if (atomicAdd(&g_cnt, 1) == gridDim.x - 1) {
            atomicExch(&g_cnt, 0);
            __threadfence();
            g_gen = gen + 1;
        } else {
            while (g_gen == gen) { __nanosleep(32); }
        }
        __threadfence();
    }
    __syncthreads();
}

__device__ __forceinline__ ull fma2(ull a, ull b, ull c) {
    ull d; asm("fma.rn.f32x2 %0,%1,%2,%3;" : "=l"(d) : "l"(a), "l"(b), "l"(c));
    return d;
}
__device__ __forceinline__ ull mul2(ull a, ull b) {
    ull d; asm("mul.rn.f32x2 %0,%1,%2;" : "=l"(d) : "l"(a), "l"(b));
    return d;
}
__device__ __forceinline__ ull pk2(float x, float y) {
    ull d; asm("mov.b64 %0,{%1,%2};" : "=l"(d) : "f"(x), "f"(y));
    return d;
}
__device__ __forceinline__ float2 unpk(ull v) {
    float2 r; asm("mov.b64 {%0,%1},%2;" : "=f"(r.x), "=f"(r.y) : "l"(v));
    return r;
}
__device__ __forceinline__ float wsum(float v) {
#pragma unroll
    for (int o = 16; o; o >>= 1) v += __shfl_xor_sync(0xffffffffu, v, o);
    return v;
}
__device__ __forceinline__ float wmax(float v) {
#pragma unroll
    for (int o = 16; o; o >>= 1) v = fmaxf(v, __shfl_xor_sync(0xffffffffu, v, o));
    return v;
}
// 32B global load (LDG.256), pin in L2 (evict_last) — v4.b64 is the only
// vector width ptxas accepts with L2::evict_last on sm_103.
__device__ __forceinline__ ulonglong4 ldg_el(const void* p) {
    ulonglong4 r;
    asm("ld.global.nc.L2::evict_last.v4.b64 {%0,%1,%2,%3},[%4];"
        : "=l"(r.x), "=l"(r.y), "=l"(r.z), "=l"(r.w) : "l"(p));
    return r;
}

__global__ void __launch_bounds__(NTHR, 1) speller_kernel(
    const float* __restrict__ L,
    const float* __restrict__ W_ih,
    const float* __restrict__ W_hh,
    const float* __restrict__ b_ih,
    const float* __restrict__ b_hh,
    const float* __restrict__ W_out,
    const float* __restrict__ b_out,
    float* __restrict__ out_logp,
    float* __restrict__ out_attn)
{
    const int tid  = threadIdx.x;
    const int bid  = blockIdx.x;
    const int wid  = tid >> 5;
    const int lane = tid & 31;

    extern __shared__ float sm[];
    float* s_h      = sm + OFF_H;
    float* s_hc     = sm + OFF_HC;
    float* s_pm     = sm + OFF_PM;
    float* s_ps     = sm + OFF_PS;
    float* s_wgt    = sm + OFF_WGT;
    float* s_logits = sm + OFF_LOG;
    float* s_MS     = sm + OFF_MS;

    // ---------------- init ----------------
    for (int i = bid * NTHR + tid; i < Bq * Hh; i += NBLK * NTHR)
        (&g_c[0][0][0])[i] = 0.f;
    for (int i = bid * NTHR + tid; i < Bq * KK; i += NBLK * NTHR) {
        int bb = i / KK, k = i - bb * KK;
        float v = 0.f;
        if (k == 0) v = 1.f;
        else if (k >= Vv && k < XD) v = L[(size_t)bb * Tt * Dd + (k - Vv)];
        g_xh[bb][k] = v;
    }
    grid_sync();

    for (int s = 0; s < Ss; ++s) {
        const int crd = s & 1, cwr = crd ^ 1;

        // ========== P1: gates = Xh @ W^T, batch-in-lanes ==========
        {
            // stage X[32][1088] -> sX[32][1092-padded] (coalesced)
            const float4* src = (const float4*)(&g_xh[0][0]);
            float4* sX4 = (float4*)sm;
            for (int idx = tid; idx < 32 * 272; idx += NTHR) {
                int bb = idx / 272, c = idx - bb * 272;
                sX4[bb * 273 + c] = src[idx];
            }
            // stage W rows [bid*16 .. +16) : sW[16][1088] = [W_ih row | W_hh row]
            float4* sW4 = (float4*)(sm + OFF_B);
            const float4* wi4 = (const float4*)W_ih + (size_t)(bid * 16) * 144;
            for (int idx = tid; idx < 16 * 144; idx += NTHR) {
                int jj = idx / 144, c = idx - jj * 144;
                sW4[jj * 272 + c] = wi4[idx];
            }
            const float4* wh4 = (const float4*)W_hh + (size_t)(bid * 16) * 128;
            for (int idx = tid; idx < 16 * 128; idx += NTHR) {
                int jj = idx / 128, c = idx - jj * 128;
                sW4[jj * 272 + 144 + c] = wh4[idx];
            }
            __syncthreads();

            const int jg = wid >> 3, kq = wid & 7;
            const bool ih = (kq < 4);
            const int nIt  = ih ? 36 : 32;
            const int koff = ih ? kq * 144 : 576 + (kq - 4) * 128;
            const float* xp  = sm + lane * 1092 + koff;
            const float* wp0 = sm + OFF_B + (jg * 8) * 1088 + koff;

            ull acc[8];
#pragma unroll
            for (int jj = 0; jj < 8; ++jj) acc[jj] = 0ull;

#pragma unroll 4
            for (int i = 0; i < nIt; ++i) {
                ulonglong2 x = *(const ulonglong2*)(xp + 4 * i);
                const float* wr = wp0 + 4 * i;
#pragma unroll
                for (int jj = 0; jj < 8; ++jj) {
                    ulonglong2 w = *(const ulonglong2*)(wr + jj * 1088);
                    acc[jj] = fma2(w.x, x.x, acc[jj]);
                    acc[jj] = fma2(w.y, x.y, acc[jj]);
                }
            }
            __syncthreads();                 // sW reads done before sp overwrite
            float* sp = sm + OFF_B;          // sp[16][8][32]
#pragma unroll
            for (int jj = 0; jj < 8; ++jj) {
                float2 p = unpk(acc[jj]);
                sp[((jg * 8 + jj) * 8 + kq) * 32 + lane] = p.x + p.y;
            }
            __syncthreads();
            {   // k-partial reduce: warp=j, lane=b
                float v = 0.f;
#pragma unroll
                for (int q = 0; q < 8; ++q) v += sp[(wid * 8 + q) * 32 + lane];
                const int j = bid * 16 + wid;
                g_gates[lane][j] = v + b_ih[j] + b_hh[j];
            }
        }
        grid_sync();

        // ========== P2: LSTM cell + flash attention, 2-t rounds ==========
        {
            const int b = bid >> 2, part = bid & 3;
            {
                const int k = tid;
                float ig = g_gates[b][k];
                float fg = g_gates[b][512 + k];
                float gg = g_gates[b][1024 + k];
                float og = g_gates[b][1536 + k];
                float iv = 1.f / (1.f + __expf(-ig));
                float fv = 1.f / (1.f + __expf(-fg));
                float gv = tanhf(gg);
                float ov = 1.f / (1.f + __expf(-og));
                float cn = fv * g_c[crd][b][k] + iv * gv;
                float hn = ov * tanhf(cn);
                s_h[k] = hn;
                if (part == 0) { g_c[cwr][b][k] = cn; g_xh[b][XD + k] = hn; }
            }
            __syncthreads();

            // pack h: lane owns floats [8*lane, 8*lane+8) of each 256-float half
            ull H[8];
            {
                const ulonglong2* h2 = (const ulonglong2*)s_h;
                ulonglong2 a = h2[2 * lane], bq2 = h2[2 * lane + 1];
                ulonglong2 c2 = h2[64 + 2 * lane], d2 = h2[64 + 2 * lane + 1];
                H[0] = a.x;  H[1] = a.y;  H[2] = bq2.x; H[3] = bq2.y;
                H[4] = c2.x; H[5] = c2.y; H[6] = d2.x;  H[7] = d2.y;
            }
            const char* Lb = (const char*)L + (size_t)b * Tt * Dd * 4;
            const int t0 = part * 256 + wid * 16;
            float m = -INFINITY, ss = 0.f;
            ull V[8];
#pragma unroll
            for (int q = 0; q < 8; ++q) V[q] = 0ull;

            for (int r = 0; r < 8; ++r) {
                const int t = t0 + 2 * r;
                const char* p0 = Lb + (size_t)t * 2048 + lane * 32;
                ulonglong4 A0 = ldg_el(p0);            // t,   lo half
                ulonglong4 A1 = ldg_el(p0 + 1024);     // t,   hi half
                ulonglong4 B0 = ldg_el(p0 + 2048);     // t+1, lo half
                ulonglong4 B1 = ldg_el(p0 + 3072);     // t+1, hi half

                ull ea2 = mul2(A0.x, H[0]);
                ea2 = fma2(A0.y, H[1], ea2); ea2 = fma2(A0.z, H[2], ea2);
                ea2 = fma2(A0.w, H[3], ea2); ea2 = fma2(A1.x, H[4], ea2);
                ea2 = fma2(A1.y, H[5], ea2); ea2 = fma2(A1.z, H[6], ea2);
                ea2 = fma2(A1.w, H[7], ea2);
                ull eb2 = mul2(B0.x, H[0]);
                eb2 = fma2(B0.y, H[1], eb2); eb2 = fma2(B0.z, H[2], eb2);
                eb2 = fma2(B0.w, H[3], eb2); eb2 = fma2(B1.x, H[4], eb2);
                eb2 = fma2(B1.y, H[5], eb2); eb2 = fma2(B1.z, H[6], eb2);
                eb2 = fma2(B1.w, H[7], eb2);

                float2 fa = unpk(ea2), fb = unpk(eb2);
                float ea = fa.x + fa.y, eb = fb.x + fb.y;
#pragma unroll
                for (int o = 16; o; o >>= 1) {
                    ea += __shfl_xor_sync(0xffffffffu, ea, o);
                    eb += __shfl_xor_sync(0xffffffffu, eb, o);
                }
                if (lane == 0) { g_e[b][t] = ea; g_e[b][t + 1] = eb; }

                if (ea > m) {
                    float sc = __expf(m - ea); ull sc2 = pk2(sc, sc);
                    ss = ss * sc + 1.f;
                    V[0] = fma2(V[0], sc2, A0.x); V[1] = fma2(V[1], sc2, A0.y);
                    V[2] = fma2(V[2], sc2, A0.z); V[3] = fma2(V[3], sc2, A0.w);
                    V[4] = fma2(V[4], sc2, A1.x); V[5] = fma2(V[5], sc2, A1.y);
                    V[6] = fma2(V[6], sc2, A1.z); V[7] = fma2(V[7], sc2, A1.w);
                    m = ea;
                } else {
                    float w = __expf(ea - m); ull w2 = pk2(w, w);
                    ss += w;
                    V[0] = fma2(A0.x, w2, V[0]); V[1] = fma2(A0.y, w2, V[1]);
                    V[2] = fma2(A0.z, w2, V[2]); V[3] = fma2(A0.w, w2, V[3]);
                    V[4] = fma2(A1.x, w2, V[4]); V[5] = fma2(A1.y, w2, V[5]);
                    V[6] = fma2(A1.z, w2, V[6]); V[7] = fma2(A1.w, w2, V[7]);
                }
                if (eb > m) {
                    float sc = __expf(m - eb); ull sc2 = pk2(sc, sc);
                    ss = ss * sc + 1.f;
                    V[0] = fma2(V[0], sc2, B0.x); V[1] = fma2(V[1], sc2, B0.y);
                    V[2] = fma2(V[2], sc2, B0.z); V[3] = fma2(V[3], sc2, B0.w);
                    V[4] = fma2(V[4], sc2, B1.x); V[5] = fma2(V[5], sc2, B1.y);
                    V[6] = fma2(V[6], sc2, B1.z); V[7] = fma2(V[7], sc2, B1.w);
                    m = eb;
                } else {
                    float w = __expf(eb - m); ull w2 = pk2(w, w);
                    ss += w;
                    V[0] = fma2(B0.x, w2, V[0]); V[1] = fma2(B0.y, w2, V[1]);
                    V[2] = fma2(B0.z, w2, V[2]); V[3] = fma2(B0.w, w2, V[3]);
                    V[4] = fma2(B1.x, w2, V[4]); V[5] = fma2(B1.y, w2, V[5]);
                    V[6] = fma2(B1.z, w2, V[6]); V[7] = fma2(B1.w, w2, V[7]);
                }
            }
            // per-warp partial -> s_pv (region A); layout matches H coverage:
            // floats [8*lane, 8*lane+8) of each 256-float half
            float* s_pv = sm;
            {
                ulonglong2* pv2 = (ulonglong2*)(s_pv + (wid << 9));
                ulonglong2 t2;
                t2.x = V[0]; t2.y = V[1]; pv2[2 * lane]          = t2;
                t2.x = V[2]; t2.y = V[3]; pv2[2 * lane + 1]      = t2;
                t2.x = V[4]; t2.y = V[5]; pv2[64 + 2 * lane]     = t2;
                t2.x = V[6]; t2.y = V[7]; pv2[64 + 2 * lane + 1] = t2;
                if (lane == 0) { s_pm[wid] = m; s_ps[wid] = ss; }
            }
            __syncthreads();
            if (wid == 0) {
                float mi = (lane < 16) ? s_pm[lane] : -INFINITY;
                float M = wmax(mi);
                float wg = (lane < 16) ? __expf(mi - M) : 0.f;
                if (lane < 16) s_wgt[lane] = wg;
                float sw = wsum((lane < 16) ? s_ps[lane] * wg : 0.f);
                if (lane == 0) { g_pm[b * 4 + part] = M; g_ps[b * 4 + part] = sw; }
            }
            __syncthreads();
            {
                float acc = 0.f;
#pragma unroll
                for (int w = 0; w < 16; ++w)
                    acc += s_wgt[w] * s_pv[(w << 9) + tid];
                g_pvm[b][part][tid] = acc;
            }
        }
        grid_sync();

        // ========== P3: merge + record (all blocks) + head (part0) ==========
        {
            const int b = bid >> 2, part = bid & 3;
            if (wid == 0) {
                float mi = (lane < 4) ? g_pm[b * 4 + lane] : -INFINITY;
                float M = wmax(mi);
                float wg = (lane < 4) ? __expf(mi - M) : 0.f;
                if (lane < 4) s_wgt[lane] = wg;
                float S = wsum((lane < 4) ? g_ps[b * 4 + lane] * wg : 0.f);
                if (lane == 0) { s_MS[0] = M; s_MS[1] = 1.f / S; }
            }
            __syncthreads();
            const float M = s_MS[0], invS = s_MS[1];

            if (tid < 256) {
                const int t = part * 256 + tid;
                out_attn[((size_t)s * Bq + b) * Tt + t] =
                    __expf(g_e[b][t] - M) * invS;
            }

            if (part == 0) {
                {
                    const int d = tid;
                    float acc = s_wgt[0] * g_pvm[b][0][d] + s_wgt[1] * g_pvm[b][1][d]
                              + s_wgt[2] * g_pvm[b][2][d] + s_wgt[3] * g_pvm[b][3][d];
                    float ctx = acc * invS;
                    s_hc[Hh + d] = ctx;
                    g_xh[b][Vv + d] = ctx;
                    s_hc[d] = g_xh[b][XD + d];
                }
                __syncthreads();
                {
                    ull C[16];
                    const ulonglong2* hc2 = (const ulonglong2*)s_hc;
#pragma unroll
                    for (int q = 0; q < 8; ++q) {
                        ulonglong2 t2 = hc2[lane + (q << 5)];
                        C[2 * q] = t2.x; C[2 * q + 1] = t2.y;
                    }
#pragma unroll
                    for (int rr = 0; rr < 4; ++rr) {
                        const int r = (wid << 2) | rr;
                        const ulonglong2* wr = (const ulonglong2*)(W_out + (size_t)r * 2 * Hh);
                        ull e2 = 0ull;
#pragma unroll
                        for (int q = 0; q < 8; ++q) {
                            ulonglong2 w2 = wr[lane + (q << 5)];
                            e2 = fma2(w2.x, C[2 * q], e2);
                            e2 = fma2(w2.y, C[2 * q + 1], e2);
                        }
                        float2 p = unpk(e2);
                        float v = wsum(p.x + p.y);
                        if (lane == 0) s_logits[r] = v + b_out[r];
                    }
                }
                __syncthreads();
                if (tid < 32) {
                    float z0 = s_logits[tid], z1 = s_logits[32 + tid];
                    float zm = wmax(fmaxf(z0, z1));
                    float es = wsum(__expf(z0 - zm) + __expf(z1 - zm));
                    float lse = zm + logf(es);
                    float* lp = out_logp + ((size_t)s * Bq + b) * Vv;
                    lp[tid]      = z0 - lse;
                    lp[32 + tid] = z1 - lse;
                    float bv; int bi2;
                    if (z1 > z0) { bv = z1; bi2 = 32 + tid; } else { bv = z0; bi2 = tid; }
#pragma unroll
                    for (int o = 16; o; o >>= 1) {
                        float ov = __shfl_xor_sync(0xffffffffu, bv, o);
                        int   oi = __shfl_xor_sync(0xffffffffu, bi2, o);
                        if (ov > bv || (ov == bv && oi < bi2)) { bv = ov; bi2 = oi; }
                    }
                    g_xh[b][tid]      = (tid == bi2)      ? 1.f : 0.f;
                    g_xh[b][32 + tid] = (32 + tid == bi2) ? 1.f : 0.f;
                }
            }
        }
        grid_sync();
    }
}

extern "C" void kernel_launch(void* const* d_in, const int* in_sizes, int n_in,
                              void* d_out, int out_size) {
    const float* L     = (const float*)d_in[0];
    const float* W_ih  = (const float*)d_in[1];
    const float* W_hh  = (const float*)d_in[2];
    const float* b_ih  = (const float*)d_in[3];
    const float* b_hh  = (const float*)d_in[4];
    const float* W_out = (const float*)d_in[5];
    const float* b_out = (const float*)d_in[6];
    float* out_logp = (float*)d_out;
    float* out_attn = (float*)d_out + (size_t)Ss * Bq * Vv;
    const int smem_bytes = SMEM_FLOATS * 4;
    cudaFuncSetAttribute(speller_kernel,
                         cudaFuncAttributeMaxDynamicSharedMemorySize, smem_bytes);
    speller_kernel<<<NBLK, NTHR, smem_bytes>>>(L, W_ih, W_hh, b_ih, b_hh,
                                               W_out, b_out, out_logp, out_attn);
}

// round 6
// speedup vs baseline: 2.6939x; 1.1237x over previous
#include <cuda_runtime.h>
#include <math.h>

#define Bq   32
#define Tt   1024
#define Dd   512
#define Hh   512
#define Vv   64
#define Ss   128
#define XD   576      /* V + H */
#define KK   1088     /* XD + H */
#define G4   2048
#define NBLK 128
#define NTHR 512

typedef unsigned long long ull;

// smem layout (float offsets)
#define OFF_A   0        /* 34944: P1 sX[32][1092] then sp[16][8][32]; P2 s_pv[16][512] */
#define OFF_B   34944    /* 17408: sW[16][1088]  — staged ONCE, persists all steps */
#define OFF_H   52352    /* 512  */
#define OFF_HC  52864    /* 1024 */
#define OFF_PM  53888    /* 16   */
#define OFF_PS  53904    /* 16   */
#define OFF_WGT 53920    /* 16   */
#define OFF_LOG 53936    /* 64   */
#define OFF_MS  54000    /* 2    */
#define OFF_E   54004    /* 256  */
#define SMEM_FLOATS 54260

// ---------------- device scratch ----------------
__device__ float g_xh[Bq][KK];          // [onehot(64) | ctx(512) | h(512)]
__device__ float g_c[2][Bq][Hh];
__device__ float g_gates[Bq][G4];
__device__ float g_pm[Bq * 4];
__device__ float g_ps[Bq * 4];
__device__ float g_pvm[Bq][4][Dd];
__device__ unsigned g_bcnt[Bq];

__device__ unsigned g_cnt = 0;
__device__ volatile unsigned g_gen = 0;

__device__ __forceinline__ void grid_sync() {
    __threadfence();
    __syncthreads();
    if (threadIdx.x == 0) {
        unsigned gen = g_gen;
        if (atomicAdd(&g_cnt, 1) == gridDim.x - 1) {
            atomicExch(&g_cnt, 0);
            __threadfence();
            g_gen = gen + 1;
        } else {
            while (g_gen == gen) { __nanosleep(16); }
        }
        __threadfence();
    }
    __syncthreads();
}

__device__ __forceinline__ ull fma2(ull a, ull b, ull c) {
    ull d; asm("fma.rn.f32x2 %0,%1,%2,%3;" : "=l"(d) : "l"(a), "l"(b), "l"(c));
    return d;
}
__device__ __forceinline__ ull mul2(ull a, ull b) {
    ull d; asm("mul.rn.f32x2 %0,%1,%2;" : "=l"(d) : "l"(a), "l"(b));
    return d;
}
__device__ __forceinline__ ull pk2(float x, float y) {
    ull d; asm("mov.b64 %0,{%1,%2};" : "=l"(d) : "f"(x), "f"(y));
    return d;
}
__device__ __forceinline__ float2 unpk(ull v) {
    float2 r; asm("mov.b64 {%0,%1},%2;" : "=f"(r.x), "=f"(r.y) : "l"(v));
    return r;
}
__device__ __forceinline__ float wsum(float v) {
#pragma unroll
    for (int o = 16; o; o >>= 1) v += __shfl_xor_sync(0xffffffffu, v, o);
    return v;
}
__device__ __forceinline__ float wmax(float v) {
#pragma unroll
    for (int o = 16; o; o >>= 1) v = fmaxf(v, __shfl_xor_sync(0xffffffffu, v, o));
    return v;
}
// 32B global load (LDG.256), pin in L2 (evict_last)
__device__ __forceinline__ ulonglong4 ldg_el(const void* p) {
    ulonglong4 r;
    asm("ld.global.nc.L2::evict_last.v4.b64 {%0,%1,%2,%3},[%4];"
        : "=l"(r.x), "=l"(r.y), "=l"(r.z), "=l"(r.w) : "l"(p));
    return r;
}
// L1-bypassing loads for cross-block communication (no stale L1 hits)
__device__ __forceinline__ float ldcv(const float* p) {
    float v; asm("ld.global.cv.f32 %0,[%1];" : "=f"(v) : "l"(p));
    return v;
}
__device__ __forceinline__ float4 ldcv4(const float4* p) {
    float4 v;
    asm("ld.global.cv.v4.f32 {%0,%1,%2,%3},[%4];"
        : "=f"(v.x), "=f"(v.y), "=f"(v.z), "=f"(v.w) : "l"(p));
    return v;
}

__global__ void __launch_bounds__(NTHR, 1) speller_kernel(
    const float* __restrict__ L,
    const float* __restrict__ W_ih,
    const float* __restrict__ W_hh,
    const float* __restrict__ b_ih,
    const float* __restrict__ b_hh,
    const float* __restrict__ W_out,
    const float* __restrict__ b_out,
    float* __restrict__ out_logp,
    float* __restrict__ out_attn)
{
    const int tid  = threadIdx.x;
    const int bid  = blockIdx.x;
    const int wid  = tid >> 5;
    const int lane = tid & 31;
    const int b    = bid >> 2, part = bid & 3;

    extern __shared__ float sm[];
    float* s_h      = sm + OFF_H;
    float* s_hc     = sm + OFF_HC;
    float* s_pm     = sm + OFF_PM;
    float* s_ps     = sm + OFF_PS;
    float* s_wgt    = sm + OFF_WGT;
    float* s_logits = sm + OFF_LOG;
    float* s_MS     = sm + OFF_MS;
    float* s_e      = sm + OFF_E;

    // ---------------- init ----------------
    for (int i = bid * NTHR + tid; i < Bq * Hh; i += NBLK * NTHR)
        (&g_c[0][0][0])[i] = 0.f;
    for (int i = bid * NTHR + tid; i < Bq * KK; i += NBLK * NTHR) {
        int bb = i / KK, k = i - bb * KK;
        float v = 0.f;
        if (k == 0) v = 1.f;
        else if (k >= Vv && k < XD) v = L[(size_t)bb * Tt * Dd + (k - Vv)];
        g_xh[bb][k] = v;
    }
    if (tid == 0 && part == 0) g_bcnt[b] = 0;   // replay-safe local-sync counter

    // stage W rows [bid*16 .. +16) ONCE: sW[16][1088] = [W_ih row | W_hh row]
    {
        float4* sW4 = (float4*)(sm + OFF_B);
        const float4* wi4 = (const float4*)W_ih + (size_t)(bid * 16) * 144;
        for (int idx = tid; idx < 16 * 144; idx += NTHR) {
            int jj = idx / 144, c = idx - jj * 144;
            sW4[jj * 272 + c] = wi4[idx];
        }
        const float4* wh4 = (const float4*)W_hh + (size_t)(bid * 16) * 128;
        for (int idx = tid; idx < 16 * 128; idx += NTHR) {
            int jj = idx / 128, c = idx - jj * 128;
            sW4[jj * 272 + 144 + c] = wh4[idx];
        }
    }
    grid_sync();

    for (int s = 0; s < Ss; ++s) {
        const int crd = s & 1, cwr = crd ^ 1;

        // ========== P1: gates = Xh @ W^T, batch-in-lanes ==========
        {
            // stage X[32][1088] -> sX[32][1092-padded], L1-bypassing (fresh)
            const float4* src = (const float4*)(&g_xh[0][0]);
            float4* sX4 = (float4*)sm;
            for (int idx = tid; idx < 32 * 272; idx += NTHR) {
                int bb = idx / 272, c = idx - bb * 272;
                sX4[bb * 273 + c] = ldcv4(src + idx);
            }
            __syncthreads();

            const int jg = wid >> 3, kq = wid & 7;
            const bool ih = (kq < 4);
            const int nIt  = ih ? 36 : 32;
            const int koff = ih ? kq * 144 : 576 + (kq - 4) * 128;
            const float* xp  = sm + lane * 1092 + koff;
            const float* wp0 = sm + OFF_B + (jg * 8) * 1088 + koff;

            ull acc[8];
#pragma unroll
            for (int jj = 0; jj < 8; ++jj) acc[jj] = 0ull;

#pragma unroll 4
            for (int i = 0; i < nIt; ++i) {
                ulonglong2 x = *(const ulonglong2*)(xp + 4 * i);
                const float* wr = wp0 + 4 * i;
#pragma unroll
                for (int jj = 0; jj < 8; ++jj) {
                    ulonglong2 w = *(const ulonglong2*)(wr + jj * 1088);
                    acc[jj] = fma2(w.x, x.x, acc[jj]);
                    acc[jj] = fma2(w.y, x.y, acc[jj]);
                }
            }
            __syncthreads();                 // sX reads done; reuse region A
            float* sp = sm;                  // sp[16][8][32] overwrites dead sX
#pragma unroll
            for (int jj = 0; jj < 8; ++jj) {
                float2 p = unpk(acc[jj]);
                sp[((jg * 8 + jj) * 8 + kq) * 32 + lane] = p.x + p.y;
            }
            __syncthreads();
            {   // k-partial reduce: warp=j, lane=b
                float v = 0.f;
#pragma unroll
                for (int q = 0; q < 8; ++q) v += sp[(wid * 8 + q) * 32 + lane];
                const int j = bid * 16 + wid;
                g_gates[lane][j] = v + b_ih[j] + b_hh[j];
            }
        }
        grid_sync();

        // ========== P2: LSTM cell + flash attention + merged P3 ==========
        {
            {   // cell update: one element per thread (fresh gate reads)
                const int k = tid;
                float ig = ldcv(&g_gates[b][k]);
                float fg = ldcv(&g_gates[b][512 + k]);
                float gg = ldcv(&g_gates[b][1024 + k]);
                float og = ldcv(&g_gates[b][1536 + k]);
                float cp = ldcv(&g_c[crd][b][k]);
                float iv = 1.f / (1.f + __expf(-ig));
                float fv = 1.f / (1.f + __expf(-fg));
                float gv = tanhf(gg);
                float ov = 1.f / (1.f + __expf(-og));
                float cn = fv * cp + iv * gv;
                float hn = ov * tanhf(cn);
                s_h[k] = hn;
                if (part == 0) { g_c[cwr][b][k] = cn; g_xh[b][XD + k] = hn; }
            }
            __syncthreads();

            // pack h: lane owns floats [8*lane, 8*lane+8) of each 256-float half
            ull H[8];
            {
                const ulonglong2* h2 = (const ulonglong2*)s_h;
                ulonglong2 a = h2[2 * lane], bq2 = h2[2 * lane + 1];
                ulonglong2 c2 = h2[64 + 2 * lane], d2 = h2[64 + 2 * lane + 1];
                H[0] = a.x;  H[1] = a.y;  H[2] = bq2.x; H[3] = bq2.y;
                H[4] = c2.x; H[5] = c2.y; H[6] = d2.x;  H[7] = d2.y;
            }
            const char* Lb = (const char*)L + (size_t)b * Tt * Dd * 4;
            const int t0 = part * 256 + wid * 16;
            float m = -INFINITY, ss = 0.f;
            ull V[8];
#pragma unroll
            for (int q = 0; q < 8; ++q) V[q] = 0ull;

            for (int r = 0; r < 8; ++r) {
                const int t = t0 + 2 * r;
                const char* p0 = Lb + (size_t)t * 2048 + lane * 32;
                ulonglong4 A0 = ldg_el(p0);
                ulonglong4 A1 = ldg_el(p0 + 1024);
                ulonglong4 B0 = ldg_el(p0 + 2048);
                ulonglong4 B1 = ldg_el(p0 + 3072);

                ull ea2 = mul2(A0.x, H[0]);
                ea2 = fma2(A0.y, H[1], ea2); ea2 = fma2(A0.z, H[2], ea2);
                ea2 = fma2(A0.w, H[3], ea2); ea2 = fma2(A1.x, H[4], ea2);
                ea2 = fma2(A1.y, H[5], ea2); ea2 = fma2(A1.z, H[6], ea2);
                ea2 = fma2(A1.w, H[7], ea2);
                ull eb2 = mul2(B0.x, H[0]);
                eb2 = fma2(B0.y, H[1], eb2); eb2 = fma2(B0.z, H[2], eb2);
                eb2 = fma2(B0.w, H[3], eb2); eb2 = fma2(B1.x, H[4], eb2);
                eb2 = fma2(B1.y, H[5], eb2); eb2 = fma2(B1.z, H[6], eb2);
                eb2 = fma2(B1.w, H[7], eb2);

                float2 fa = unpk(ea2), fb = unpk(eb2);
                float ea = fa.x + fa.y, eb = fb.x + fb.y;
#pragma unroll
                for (int o = 16; o; o >>= 1) {
                    ea += __shfl_xor_sync(0xffffffffu, ea, o);
                    eb += __shfl_xor_sync(0xffffffffu, eb, o);
                }
                if (lane == 0) {
                    s_e[wid * 16 + 2 * r]     = ea;
                    s_e[wid * 16 + 2 * r + 1] = eb;
                }

                if (ea > m) {
                    float sc = __expf(m - ea); ull sc2 = pk2(sc, sc);
                    ss = ss * sc + 1.f;
                    V[0] = fma2(V[0], sc2, A0.x); V[1] = fma2(V[1], sc2, A0.y);
                    V[2] = fma2(V[2], sc2, A0.z); V[3] = fma2(V[3], sc2, A0.w);
                    V[4] = fma2(V[4], sc2, A1.x); V[5] = fma2(V[5], sc2, A1.y);
                    V[6] = fma2(V[6], sc2, A1.z); V[7] = fma2(V[7], sc2, A1.w);
                    m = ea;
                } else {
                    float w = __expf(ea - m); ull w2 = pk2(w, w);
                    ss += w;
                    V[0] = fma2(A0.x, w2, V[0]); V[1] = fma2(A0.y, w2, V[1]);
                    V[2] = fma2(A0.z, w2, V[2]); V[3] = fma2(A0.w, w2, V[3]);
                    V[4] = fma2(A1.x, w2, V[4]); V[5] = fma2(A1.y, w2, V[5]);
                    V[6] = fma2(A1.z, w2, V[6]); V[7] = fma2(A1.w, w2, V[7]);
                }
                if (eb > m) {
                    float sc = __expf(m - eb); ull sc2 = pk2(sc, sc);
                    ss = ss * sc + 1.f;
                    V[0] = fma2(V[0], sc2, B0.x); V[1] = fma2(V[1], sc2, B0.y);
                    V[2] = fma2(V[2], sc2, B0.z); V[3] = fma2(V[3], sc2, B0.w);
                    V[4] = fma2(V[4], sc2, B1.x); V[5] = fma2(V[5], sc2, B1.y);
                    V[6] = fma2(V[6], sc2, B1.z); V[7] = fma2(V[7], sc2, B1.w);
                    m = eb;
                } else {
                    float w = __expf(eb - m); ull w2 = pk2(w, w);
                    ss += w;
                    V[0] = fma2(B0.x, w2, V[0]); V[1] = fma2(B0.y, w2, V[1]);
                    V[2] = fma2(B0.z, w2, V[2]); V[3] = fma2(B0.w, w2, V[3]);
                    V[4] = fma2(B1.x, w2, V[4]); V[5] = fma2(B1.y, w2, V[5]);
                    V[6] = fma2(B1.z, w2, V[6]); V[7] = fma2(B1.w, w2, V[7]);
                }
            }
            // per-warp partial -> s_pv (region A)
            float* s_pv = sm;
            {
                ulonglong2* pv2 = (ulonglong2*)(s_pv + (wid << 9));
                ulonglong2 t2;
                t2.x = V[0]; t2.y = V[1]; pv2[2 * lane]          = t2;
                t2.x = V[2]; t2.y = V[3]; pv2[2 * lane + 1]      = t2;
                t2.x = V[4]; t2.y = V[5]; pv2[64 + 2 * lane]     = t2;
                t2.x = V[6]; t2.y = V[7]; pv2[64 + 2 * lane + 1] = t2;
                if (lane == 0) { s_pm[wid] = m; s_ps[wid] = ss; }
            }
            __syncthreads();
            if (wid == 0) {
                float mi = (lane < 16) ? s_pm[lane] : -INFINITY;
                float M = wmax(mi);
                float wg = (lane < 16) ? __expf(mi - M) : 0.f;
                if (lane < 16) s_wgt[lane] = wg;
                float sw = wsum((lane < 16) ? s_ps[lane] * wg : 0.f);
                if (lane == 0) { g_pm[b * 4 + part] = M; g_ps[b * 4 + part] = sw; }
            }
            __syncthreads();
            {
                float acc = 0.f;
#pragma unroll
                for (int w = 0; w < 16; ++w)
                    acc += s_wgt[w] * s_pv[(w << 9) + tid];
                g_pvm[b][part][tid] = acc;
            }

            // ----- local sync among the 4 blocks of this batch -----
            __threadfence();
            __syncthreads();
            if (tid == 0) {
                atomicAdd(&g_bcnt[b], 1u);
                const unsigned tgt = 4u * (unsigned)(s + 1);
                while (((volatile unsigned*)g_bcnt)[b] < tgt) __nanosleep(16);
            }
            __syncthreads();

            // ----- merged P3: global merge, record, head (part0) -----
            if (wid == 0) {
                float mi = (lane < 4) ? ldcv(&g_pm[b * 4 + lane]) : -INFINITY;
                float M = wmax(mi);
                float wg = (lane < 4) ? __expf(mi - M) : 0.f;
                if (lane < 4) s_wgt[lane] = wg;
                float S = wsum((lane < 4) ? ldcv(&g_ps[b * 4 + lane]) * wg : 0.f);
                if (lane == 0) { s_MS[0] = M; s_MS[1] = 1.f / S; }
            }
            __syncthreads();
            const float M = s_MS[0], invS = s_MS[1];

            if (tid < 256) {
                out_attn[((size_t)s * Bq + b) * Tt + part * 256 + tid] =
                    __expf(s_e[tid] - M) * invS;
            }

            if (part == 0) {
                {
                    const int d = tid;
                    float acc = s_wgt[0] * ldcv(&g_pvm[b][0][d])
                              + s_wgt[1] * ldcv(&g_pvm[b][1][d])
                              + s_wgt[2] * ldcv(&g_pvm[b][2][d])
                              + s_wgt[3] * ldcv(&g_pvm[b][3][d]);
                    float ctx = acc * invS;
                    s_hc[Hh + d] = ctx;
                    g_xh[b][Vv + d] = ctx;
                    s_hc[d] = s_h[d];
                }
                __syncthreads();
                {
                    ull C[16];
                    const ulonglong2* hc2 = (const ulonglong2*)s_hc;
#pragma unroll
                    for (int q = 0; q < 8; ++q) {
                        ulonglong2 t2 = hc2[lane + (q << 5)];
                        C[2 * q] = t2.x; C[2 * q + 1] = t2.y;
                    }
#pragma unroll
                    for (int rr = 0; rr < 4; ++rr) {
                        const int r = (wid << 2) | rr;
                        const ulonglong2* wr = (const ulonglong2*)(W_out + (size_t)r * 2 * Hh);
                        ull e2 = 0ull;
#pragma unroll
                        for (int q = 0; q < 8; ++q) {
                            ulonglong2 w2 = wr[lane + (q << 5)];
                            e2 = fma2(w2.x, C[2 * q], e2);
                            e2 = fma2(w2.y, C[2 * q + 1], e2);
                        }
                        float2 p = unpk(e2);
                        float v = wsum(p.x + p.y);
                        if (lane == 0) s_logits[r] = v + b_out[r];
                    }
                }
                __syncthreads();
                if (tid < 32) {
                    float z0 = s_logits[tid], z1 = s_logits[32 + tid];
                    float zm = wmax(fmaxf(z0, z1));
                    float es = wsum(__expf(z0 - zm) + __expf(z1 - zm));
                    float lse = zm + logf(es);
                    float* lp = out_logp + ((size_t)s * Bq + b) * Vv;
                    lp[tid]      = z0 - lse;
                    lp[32 + tid] = z1 - lse;
                    float bv; int bi2;
                    if (z1 > z0) { bv = z1; bi2 = 32 + tid; } else { bv = z0; bi2 = tid; }
#pragma unroll
                    for (int o = 16; o; o >>= 1) {
                        float ov = __shfl_xor_sync(0xffffffffu, bv, o);
                        int   oi = __shfl_xor_sync(0xffffffffu, bi2, o);
                        if (ov > bv || (ov == bv && oi < bi2)) { bv = ov; bi2 = oi; }
                    }
                    g_xh[b][tid]      = (tid == bi2)      ? 1.f : 0.f;
                    g_xh[b][32 + tid] = (32 + tid == bi2) ? 1.f : 0.f;
                }
            }
        }
        grid_sync();
    }
}

extern "C" void kernel_launch(void* const* d_in, const int* in_sizes, int n_in,
                              void* d_out, int out_size) {
    const float* L     = (const float*)d_in[0];
    const float* W_ih  = (const float*)d_in[1];
    const float* W_hh  = (const float*)d_in[2];
    const float* b_ih  = (const float*)d_in[3];
    const float* b_hh  = (const float*)d_in[4];
    const float* W_out = (const float*)d_in[5];
    const float* b_out = (const float*)d_in[6];
    float* out_logp = (float*)d_out;
    float* out_attn = (float*)d_out + (size_t)Ss * Bq * Vv;
    const int smem_bytes = SMEM_FLOATS * 4;
    cudaFuncSetAttribute(speller_kernel,
                         cudaFuncAttributeMaxDynamicSharedMemorySize, smem_bytes);
    speller_kernel<<<NBLK, NTHR, smem_bytes>>>(L, W_ih, W_hh, b_ih, b_hh,
                                               W_out, b_out, out_logp, out_attn);
}